// round 16
// baseline (speedup 1.0000x reference)
#include <cuda_runtime.h>
#include <cuda_bf16.h>
#include <cstdint>

// Problem constants
#define BATCH 2
#define SEQ   2048
#define DMODEL 1024
#define NHEAD 16
#define DHEAD 64

__device__ __forceinline__ float to_tf32(float a) {
    float r;
    asm("cvt.rna.tf32.f32 %0, %1;" : "=f"(r) : "f"(a));
    return r;
}
__device__ __forceinline__ float4 round4(float4 v) {
    v.x = to_tf32(v.x); v.y = to_tf32(v.y);
    v.z = to_tf32(v.z); v.w = to_tf32(v.w);
    return v;
}

// m16n8k8 tf32 mma, canonical fragment order (g=lane>>2, t=lane&3):
// a0=A[g][t] a1=A[g+8][t] a2=A[g][t+4] a3=A[g+8][t+4]
// b0=B[k=t][n=g] b1=B[k=t+4][n=g]
// c0=(g,2t) c1=(g,2t+1) c2=(g+8,2t) c3=(g+8,2t+1)
__device__ __forceinline__ void mma8(float* c, const uint32_t* a,
                                     uint32_t b0, uint32_t b1) {
    asm volatile(
        "mma.sync.aligned.m16n8k8.row.col.f32.tf32.tf32.f32 "
        "{%0,%1,%2,%3}, {%4,%5,%6,%7}, {%8,%9}, {%0,%1,%2,%3};"
        : "+f"(c[0]), "+f"(c[1]), "+f"(c[2]), "+f"(c[3])
        : "r"(a[0]), "r"(a[1]), "r"(a[2]), "r"(a[3]), "r"(b0), "r"(b1));
}
__device__ __forceinline__ void mma_tf32(float* c, uint4 a, uint32_t b0_, uint32_t b1_) {
    asm volatile(
        "mma.sync.aligned.m16n8k8.row.col.f32.tf32.tf32.f32 "
        "{%0,%1,%2,%3}, {%4,%5,%6,%7}, {%8,%9}, {%0,%1,%2,%3};"
        : "+f"(c[0]), "+f"(c[1]), "+f"(c[2]), "+f"(c[3])
        : "r"(a.x), "r"(a.z), "r"(a.y), "r"(a.w), "r"(b0_), "r"(b1_));
}

// ===========================================================================
// Scratch. q stored tf32-rounded AND pre-scaled by 0.125 (exact binade
// shift -> numerics identical to (q.k)/8). k, v stored tf32-rounded.
// g_er holds Er pre-rounded to tf32.
// ===========================================================================
__device__ float g_q[BATCH * NHEAD * SEQ * DHEAD];
__device__ float g_k[BATCH * NHEAD * SEQ * DHEAD];
__device__ float g_v[BATCH * NHEAD * SEQ * DHEAD];
__device__ float g_er[SEQ * DHEAD];
__device__ float g_wt[3 * DMODEL * DMODEL];

// ===========================================================================
// Prep: transpose + round W -> g_wt[z][n][k]
// ===========================================================================
__global__ __launch_bounds__(256) void prep_w_kernel(
    const float* __restrict__ W0, const float* __restrict__ W1,
    const float* __restrict__ W2)
{
    __shared__ float t[32][33];
    const int z = blockIdx.z;
    const float* W = (z == 0) ? W0 : (z == 1) ? W1 : W2;
    float* WT = g_wt + (size_t)z * DMODEL * DMODEL;
    const int n0 = blockIdx.x * 32;
    const int k0 = blockIdx.y * 32;
    const int tx = threadIdx.x & 31;
    const int ty = threadIdx.x >> 5;
    #pragma unroll
    for (int r = 0; r < 4; r++)
        t[ty + 8 * r][tx] = to_tf32(W[(size_t)(k0 + ty + 8 * r) * DMODEL + n0 + tx]);
    __syncthreads();
    #pragma unroll
    for (int r = 0; r < 4; r++)
        WT[(size_t)(n0 + ty + 8 * r) * DMODEL + k0 + tx] = t[tx][ty + 8 * r];
}

// ===========================================================================
// Prep: round Er to tf32
// ===========================================================================
__global__ __launch_bounds__(256) void prep_er_kernel(const float* __restrict__ Er)
{
    int i = blockIdx.x * 256 + threadIdx.x;
    ((float4*)g_er)[i] = round4(((const float4*)Er)[i]);
}

// ===========================================================================
// QKV GEMM via mma.sync tf32 (R15 winner: TKT=16, 2 CTAs/SM). Unchanged.
// ===========================================================================
#define TKT 16
#define NKT (DMODEL / TKT)        // 64
#define STAGEF 4096               // floats per stage (A 2048 + B 2048)

__global__ __launch_bounds__(256, 2) void qkv_gemm_mma_kernel(
    const float* __restrict__ x,
    const float* __restrict__ b0v, const float* __restrict__ b1v,
    const float* __restrict__ b2v)
{
    extern __shared__ float smf[];

    const int z  = blockIdx.z;
    const int m0 = blockIdx.y * 128;
    const int n0 = blockIdx.x * 128;
    const float* bias = (z == 0) ? b0v : (z == 1) ? b1v : b2v;
    float* outp       = (z == 0) ? g_q : (z == 1) ? g_k : g_v;
    const float* WT   = g_wt + (size_t)z * DMODEL * DMODEL;
    const float sc    = (z == 0) ? 0.125f : 1.0f;

    const int tid = threadIdx.x;
    const int wid = tid >> 5;
    const int lid = tid & 31;
    const int warp_m = wid >> 1;
    const int warp_n = wid & 1;
    const int g = lid >> 2;
    const int t = lid & 3;

    float acc[2][8][4];
    #pragma unroll
    for (int a = 0; a < 2; a++)
        #pragma unroll
        for (int n = 0; n < 8; n++)
            #pragma unroll
            for (int c = 0; c < 4; c++) acc[a][n][c] = 0.f;

    const int s_kc = tid >> 7;        // 0..1
    const int s_r  = tid & 127;       // 0..127
    const int s_off = s_kc * 1024 + (s_r >> 4) * 128 + (s_r & 7) * 16 + ((s_r >> 3) & 1) * 2;

    {
        const float4* pA = (const float4*)&x[(size_t)(m0 + s_r) * DMODEL + s_kc * 8];
        float4 a0 = round4(pA[0]), a1 = round4(pA[1]);
        float* dA = smf + s_off;
        *(float2*)&dA[0]  = make_float2(a0.x, a1.x);
        *(float2*)&dA[4]  = make_float2(a0.y, a1.y);
        *(float2*)&dA[8]  = make_float2(a0.z, a1.z);
        *(float2*)&dA[12] = make_float2(a0.w, a1.w);
        const float4* pB = (const float4*)&WT[(size_t)(n0 + s_r) * DMODEL + s_kc * 8];
        float4 c0 = pB[0], c1 = pB[1];
        float* dB = smf + 2048 + s_off;
        *(float2*)&dB[0]  = make_float2(c0.x, c1.x);
        *(float2*)&dB[4]  = make_float2(c0.y, c1.y);
        *(float2*)&dB[8]  = make_float2(c0.z, c1.z);
        *(float2*)&dB[12] = make_float2(c0.w, c1.w);
    }
    __syncthreads();

    for (int ktile = 0; ktile < NKT; ktile++) {
        const int buf = ktile & 1;

        float4 ra0, ra1, rb0, rb1;
        if (ktile + 1 < NKT) {
            const int kt = (ktile + 1) * TKT;
            const float4* pA = (const float4*)&x[(size_t)(m0 + s_r) * DMODEL + kt + s_kc * 8];
            ra0 = pA[0]; ra1 = pA[1];
            const float4* pB = (const float4*)&WT[(size_t)(n0 + s_r) * DMODEL + kt + s_kc * 8];
            rb0 = pB[0]; rb1 = pB[1];
        }

        const float* Ap = smf + buf * STAGEF;
        const float* Bp = Ap + 2048;
        #pragma unroll
        for (int kc = 0; kc < 2; kc++) {
            uint4 af[2];
            af[0] = *(const uint4*)&Ap[kc * 1024 + (warp_m * 2 + 0) * 128 + lid * 4];
            af[1] = *(const uint4*)&Ap[kc * 1024 + (warp_m * 2 + 1) * 128 + lid * 4];
            #pragma unroll
            for (int bp = 0; bp < 4; bp++) {
                uint4 bf = *(const uint4*)&Bp[kc * 1024 + (warp_n * 4 + bp) * 128 + lid * 4];
                #pragma unroll
                for (int amt = 0; amt < 2; amt++) {
                    mma_tf32(acc[amt][2 * bp],     af[amt], bf.x, bf.y);
                    mma_tf32(acc[amt][2 * bp + 1], af[amt], bf.z, bf.w);
                }
            }
        }

        if (ktile + 1 < NKT) {
            float* dst = smf + (buf ^ 1) * STAGEF;
            float4 a0 = round4(ra0), a1 = round4(ra1);
            float* dA = dst + s_off;
            *(float2*)&dA[0]  = make_float2(a0.x, a1.x);
            *(float2*)&dA[4]  = make_float2(a0.y, a1.y);
            *(float2*)&dA[8]  = make_float2(a0.z, a1.z);
            *(float2*)&dA[12] = make_float2(a0.w, a1.w);
            float* dB = dst + 2048 + s_off;
            *(float2*)&dB[0]  = make_float2(rb0.x, rb1.x);
            *(float2*)&dB[4]  = make_float2(rb0.y, rb1.y);
            *(float2*)&dB[8]  = make_float2(rb0.z, rb1.z);
            *(float2*)&dB[12] = make_float2(rb0.w, rb1.w);
        }
        __syncthreads();
    }

    #pragma unroll
    for (int amt = 0; amt < 2; amt++) {
        const int mA = m0 + warp_m * 32 + amt * 16 + g;
        const int bA = mA >> 11;
        const int sA = mA & (SEQ - 1);
        const int sB = (mA + 8) & (SEQ - 1);
        #pragma unroll
        for (int nt = 0; nt < 8; nt++) {
            const int n = n0 + warp_n * 64 + nt * 8 + t * 2;
            const int h = n >> 6;
            const int d = n & 63;
            const float2 bb = *(const float2*)&bias[n];
            float* p0 = &outp[(((size_t)(bA * NHEAD + h)) * SEQ + sA) * DHEAD + d];
            float* p1 = &outp[(((size_t)(bA * NHEAD + h)) * SEQ + sB) * DHEAD + d];
            *(float2*)p0 = make_float2(to_tf32((acc[amt][nt][0] + bb.x) * sc),
                                       to_tf32((acc[amt][nt][1] + bb.y) * sc));
            *(float2*)p1 = make_float2(to_tf32((acc[amt][nt][2] + bb.x) * sc),
                                       to_tf32((acc[amt][nt][3] + bb.y) * sc));
        }
    }
}

// ===========================================================================
// Relative-position causal flash attention, mma.sync tf32.
// R13/R15 structure + CIRCULAR PERSISTENT BAND: consecutive k-tiles shift the
// band window by 128 rows, so only 128 new rows are staged per tile (ti>0);
// slot = row ^ (128*(ti&1)). Band gets a dedicated region; P gets its own
// region; G overlays k_s (k dead after QK; barrier after QK added, post-REL
// barrier removed -> 3 CTA barriers/tile as before).
// SMEM: k/G[128x80|128x72] | vT[64x144, XOR-swizzle] | band[256x80, circular]
//       | P[128x132].  Total 56832 floats = 222KB.
// ===========================================================================
#define KP  80
#define VP  144
#define BP  80
#define PPL 132
#define GP  72
#define OFF_K    0
#define OFF_VT   10240             // 128*80
#define OFF_BAND 19456             // + 64*144
#define OFF_P    39936             // + 256*80
#define ATT_FLOATS 56832           // + 128*132
#define ATT_SMEM (ATT_FLOATS * 4)  // 227328

__global__ __launch_bounds__(256, 1) void relattn_mma_kernel(float* __restrict__ out)
{
    extern __shared__ float sm[];
    float* k_s  = sm + OFF_K;       // k during QK; G (stride GP) during REL
    float* vt_s = sm + OFF_VT;
    float* bd_s = sm + OFF_BAND;    // circular band
    float* p_s  = sm + OFF_P;
    float* g_s  = sm + OFF_K;       // G overlay

    const int sb = (int)gridDim.x - 1 - (int)blockIdx.x;  // heavy first
    const int bh = blockIdx.y;
    const int b  = bh >> 4;
    const int h  = bh & 15;
    const int s0 = sb * 128;

    const float* Q = g_q + (size_t)bh * SEQ * DHEAD;
    const float* K = g_k + (size_t)bh * SEQ * DHEAD;
    const float* V = g_v + (size_t)bh * SEQ * DHEAD;

    const int tid = threadIdx.x;
    const int wid = tid >> 5;
    const int lid = tid & 31;
    const int g = lid >> 2;
    const int t = lid & 3;
    const int i0 = wid * 16 + g;
    const int i1 = i0 + 8;
    const int c0b = 14 - 2 * wid;      // REL window start block (warp-uniform)

    // ---- persistent q fragments (already tf32 + 1/8-scaled) ----
    uint32_t qf[8][4];
    #pragma unroll
    for (int u = 0; u < 4; u++) {
        float4 q0 = *(const float4*)&Q[(size_t)(s0 + i0) * DHEAD + 16 * u + 4 * t];
        float4 q1 = *(const float4*)&Q[(size_t)(s0 + i1) * DHEAD + 16 * u + 4 * t];
        qf[2 * u][0] = __float_as_uint(q0.x); qf[2 * u][1] = __float_as_uint(q1.x);
        qf[2 * u][2] = __float_as_uint(q0.y); qf[2 * u][3] = __float_as_uint(q1.y);
        qf[2 * u + 1][0] = __float_as_uint(q0.z); qf[2 * u + 1][1] = __float_as_uint(q1.z);
        qf[2 * u + 1][2] = __float_as_uint(q0.w); qf[2 * u + 1][3] = __float_as_uint(q1.w);
    }

    float m_[2] = {-1e30f, -1e30f};
    float l_[2] = {0.f, 0.f};
    float acc_o[8][4];
    #pragma unroll
    for (int n8 = 0; n8 < 8; n8++)
        #pragma unroll
        for (int c = 0; c < 4; c++) acc_o[n8][c] = 0.f;

    const float4* Er4 = (const float4*)g_er;

    for (int t0 = 0; t0 <= s0; t0 += 128) {
        const bool diag = (t0 == s0);
        const int ti = t0 >> 7;
        const int bph = (ti & 1) << 7;       // circular phase for band rows
        __syncthreads();   // prior tile's QK k-reads / REL G & band reads done

        // ---- stage k, vT, band (circular: full at ti=0, 128 new rows after) ----
        {
            const float4* K4 = (const float4*)(K + (size_t)t0 * DHEAD);
            const float4* V4 = (const float4*)(V + (size_t)t0 * DHEAD);
            #pragma unroll
            for (int u = 0; u < 8; u++) {
                int f = tid + u * 256;
                int row = f >> 4, c4 = f & 15;
                *(float4*)&k_s[row * KP + c4 * 4] = K4[row * 16 + c4];
                float4 vv = V4[row * 16 + c4];
                int sw = row ^ (4 * (c4 & 3));
                vt_s[(4 * c4 + 0) * VP + sw] = vv.x;
                vt_s[(4 * c4 + 1) * VP + sw] = vv.y;
                vt_s[(4 * c4 + 2) * VP + sw] = vv.z;
                vt_s[(4 * c4 + 3) * VP + sw] = vv.w;
            }
            int l0 = t0 - s0 + (SEQ - 1) - 127;
            if (ti == 0) {
                #pragma unroll
                for (int u = 0; u < 16; u++) {
                    int f = tid + u * 256;
                    int r = f >> 4, c4 = f & 15;
                    int gl = l0 + r;
                    gl = gl > SEQ - 1 ? SEQ - 1 : gl;
                    *(float4*)&bd_s[r * BP + c4 * 4] = Er4[gl * 16 + c4];
                }
            } else {
                // new rows: logical 128..255 -> slot ((ti+1)&1)*128 + r'
                const int sl0 = ((ti + 1) & 1) << 7;
                #pragma unroll
                for (int u = 0; u < 8; u++) {
                    int f = tid + u * 256;
                    int r = f >> 4, c4 = f & 15;    // r' = 0..127
                    int gl = l0 + 128 + r;
                    gl = gl > SEQ - 1 ? SEQ - 1 : gl;
                    *(float4*)&bd_s[(sl0 + r) * BP + c4 * 4] = Er4[gl * 16 + c4];
                }
            }
        }
        __syncthreads();

        // ---- QK ----
        float acc_s[16][4];
        #pragma unroll
        for (int n8 = 0; n8 < 16; n8++)
            #pragma unroll
            for (int c = 0; c < 4; c++) acc_s[n8][c] = 0.f;

        #pragma unroll
        for (int u = 0; u < 4; u++) {
            #pragma unroll
            for (int n8 = 0; n8 < 16; n8++) {
                if (diag && n8 > 2 * wid + 1) continue;
                const uint4 kb = *(const uint4*)&k_s[(8 * n8 + g) * KP + 16 * u + 4 * t];
                mma8(acc_s[n8], qf[2 * u],     kb.x, kb.y);
                mma8(acc_s[n8], qf[2 * u + 1], kb.z, kb.w);
            }
        }
        __syncthreads();   // k reads done before G overlays k_s

        // ---- REL: uniform windowed G (3 chunks x 6 blocks) + gather ----
        #pragma unroll
        for (int ck = 0; ck < 3; ck++) {
            float acc_g[6][4];
            #pragma unroll
            for (int n6 = 0; n6 < 6; n6++)
                #pragma unroll
                for (int cc = 0; cc < 4; cc++) acc_g[n6][cc] = 0.f;

            const int bbase = c0b + 6 * ck;     // warp-uniform
            #pragma unroll
            for (int u = 0; u < 4; u++)
                #pragma unroll
                for (int n6 = 0; n6 < 6; n6++) {
                    const int brow = (8 * (bbase + n6) + g) ^ bph;   // circular slot
                    const uint4 bb = *(const uint4*)&bd_s[brow * BP + 16 * u + 4 * t];
                    mma8(acc_g[n6], qf[2 * u],     bb.x, bb.y);
                    mma8(acc_g[n6], qf[2 * u + 1], bb.z, bb.w);
                }

            __syncwarp();   // prior chunk's gather reads done (G rows warp-private)
            #pragma unroll
            for (int n6 = 0; n6 < 6; n6++) {
                *(float2*)&g_s[i0 * GP + 8 * n6 + 2 * t] = make_float2(acc_g[n6][0], acc_g[n6][1]);
                *(float2*)&g_s[i1 * GP + 8 * n6 + 2 * t] = make_float2(acc_g[n6][2], acc_g[n6][3]);
            }
            __syncwarp();

            // gather: lp = j - g + 15 - 48*ck (warp-independent)
            const int lpb = 2 * t - g + 15 - 48 * ck;
            #pragma unroll
            for (int n8 = 0; n8 < 16; n8++) {
                if (diag && n8 > 2 * wid + 1) continue;
                int lp0 = 8 * n8 + lpb;        // row i0
                int lp1 = lp0 - 8;             // row i1
                if (lp0 >= 0 && lp0 < 48)         acc_s[n8][0] += g_s[i0 * GP + lp0];
                if (lp0 + 1 >= 0 && lp0 + 1 < 48) acc_s[n8][1] += g_s[i0 * GP + lp0 + 1];
                if (lp1 >= 0 && lp1 < 48)         acc_s[n8][2] += g_s[i1 * GP + lp1];
                if (lp1 + 1 >= 0 && lp1 + 1 < 48) acc_s[n8][3] += g_s[i1 * GP + lp1 + 1];
            }
        }

        // ---- mask + row max (scale folded into q) ----
        float mx0 = -1e30f, mx1 = -1e30f;
        #pragma unroll
        for (int n8 = 0; n8 < 16; n8++) {
            int j = 8 * n8 + 2 * t;
            float v0 = acc_s[n8][0];
            float v1 = acc_s[n8][1];
            float v2 = acc_s[n8][2];
            float v3 = acc_s[n8][3];
            if (diag) {
                if (j     > i0) v0 = -1e30f;
                if (j + 1 > i0) v1 = -1e30f;
                if (j     > i1) v2 = -1e30f;
                if (j + 1 > i1) v3 = -1e30f;
            }
            acc_s[n8][0] = v0; acc_s[n8][1] = v1;
            acc_s[n8][2] = v2; acc_s[n8][3] = v3;
            mx0 = fmaxf(mx0, fmaxf(v0, v1));
            mx1 = fmaxf(mx1, fmaxf(v2, v3));
        }
        mx0 = fmaxf(mx0, __shfl_xor_sync(0xffffffffu, mx0, 1));
        mx0 = fmaxf(mx0, __shfl_xor_sync(0xffffffffu, mx0, 2));
        mx1 = fmaxf(mx1, __shfl_xor_sync(0xffffffffu, mx1, 1));
        mx1 = fmaxf(mx1, __shfl_xor_sync(0xffffffffu, mx1, 2));

        // ---- online softmax; write P (tf32) to warp-private rows ----
        float mn0 = fmaxf(m_[0], mx0);
        float mn1 = fmaxf(m_[1], mx1);
        float al0 = __expf(m_[0] - mn0);
        float al1 = __expf(m_[1] - mn1);
        m_[0] = mn0; m_[1] = mn1;
        float ls0 = 0.f, ls1 = 0.f;
        #pragma unroll
        for (int n8 = 0; n8 < 16; n8++) {
            int j = 8 * n8 + 2 * t;
            float p0 = to_tf32(__expf(acc_s[n8][0] - mn0));
            float p1 = to_tf32(__expf(acc_s[n8][1] - mn0));
            float p2 = to_tf32(__expf(acc_s[n8][2] - mn1));
            float p3 = to_tf32(__expf(acc_s[n8][3] - mn1));
            ls0 += p0 + p1;
            ls1 += p2 + p3;
            *(float2*)&p_s[i0 * PPL + j] = make_float2(p0, p1);
            *(float2*)&p_s[i1 * PPL + j] = make_float2(p2, p3);
        }
        ls0 += __shfl_xor_sync(0xffffffffu, ls0, 1);
        ls0 += __shfl_xor_sync(0xffffffffu, ls0, 2);
        ls1 += __shfl_xor_sync(0xffffffffu, ls1, 1);
        ls1 += __shfl_xor_sync(0xffffffffu, ls1, 2);
        l_[0] = l_[0] * al0 + ls0;
        l_[1] = l_[1] * al1 + ls1;
        #pragma unroll
        for (int n8 = 0; n8 < 8; n8++) {
            acc_o[n8][0] *= al0; acc_o[n8][1] *= al0;
            acc_o[n8][2] *= al1; acc_o[n8][3] *= al1;
        }
        __syncwarp();   // P rows visible within warp

        // ---- PV: O += P @ V, chunk-paired float4 loads ----
        #pragma unroll
        for (int u = 0; u < 8; u++) {
            if (diag && u > wid) continue;
            const float4 p0 = *(const float4*)&p_s[i0 * PPL + 16 * u + 4 * t];
            const float4 p1 = *(const float4*)&p_s[i1 * PPL + 16 * u + 4 * t];
            uint32_t pfA[4] = {__float_as_uint(p0.x), __float_as_uint(p1.x),
                               __float_as_uint(p0.y), __float_as_uint(p1.y)};
            uint32_t pfB[4] = {__float_as_uint(p0.z), __float_as_uint(p1.z),
                               __float_as_uint(p0.w), __float_as_uint(p1.w)};
            #pragma unroll
            for (int n8 = 0; n8 < 8; n8++) {
                int d = 8 * n8 + g;
                int xr = 4 * ((d >> 2) & 3);
                const uint4 vb = *(const uint4*)&vt_s[d * VP + (16 * u + ((4 * t) ^ xr))];
                mma8(acc_o[n8], pfA, vb.x, vb.y);
                mma8(acc_o[n8], pfB, vb.z, vb.w);
            }
        }
        __syncwarp();   // P reads done before next tile's P writes
    }

    // ---- epilogue ----
    float inv0 = 1.f / l_[0];
    float inv1 = 1.f / l_[1];
    #pragma unroll
    for (int n8 = 0; n8 < 8; n8++) {
        int d = 8 * n8 + 2 * t;
        int sg0 = s0 + i0;
        int sg1 = s0 + i1;
        *(float2*)&out[((size_t)b * SEQ + sg0) * DMODEL + h * DHEAD + d] =
            make_float2(acc_o[n8][0] * inv0, acc_o[n8][1] * inv0);
        *(float2*)&out[((size_t)b * SEQ + sg1) * DMODEL + h * DHEAD + d] =
            make_float2(acc_o[n8][2] * inv1, acc_o[n8][3] * inv1);
    }
}

// ===========================================================================
extern "C" void kernel_launch(void* const* d_in, const int* in_sizes, int n_in,
                              void* d_out, int out_size)
{
    const float* x  = (const float*)d_in[0];
    const float* Wq = (const float*)d_in[1];
    const float* bq = (const float*)d_in[2];
    const float* Wk = (const float*)d_in[3];
    const float* bk = (const float*)d_in[4];
    const float* Wv = (const float*)d_in[5];
    const float* bv = (const float*)d_in[6];
    const float* Er = (const float*)d_in[7];
    float* out = (float*)d_out;

    (void)in_sizes; (void)n_in; (void)out_size;

    cudaFuncSetAttribute(relattn_mma_kernel,
                         cudaFuncAttributeMaxDynamicSharedMemorySize, ATT_SMEM);
    const int gemm_smem = 2 * STAGEF * 4;   // 32768
    cudaFuncSetAttribute(qkv_gemm_mma_kernel,
                         cudaFuncAttributeMaxDynamicSharedMemorySize, gemm_smem);

    prep_w_kernel<<<dim3(DMODEL / 32, DMODEL / 32, 3), 256>>>(Wq, Wk, Wv);
    prep_er_kernel<<<(SEQ * DHEAD) / (4 * 256), 256>>>(Er);

    dim3 gg(DMODEL / 128, (BATCH * SEQ) / 128, 3);
    qkv_gemm_mma_kernel<<<gg, 256, gemm_smem>>>(x, bq, bk, bv);

    dim3 g2(SEQ / 128, BATCH * NHEAD);
    relattn_mma_kernel<<<g2, 256, ATT_SMEM>>>(out);
}

// round 17
// speedup vs baseline: 1.4559x; 1.4559x over previous
#include <cuda_runtime.h>
#include <cuda_bf16.h>
#include <cstdint>

// Problem constants
#define BATCH 2
#define SEQ   2048
#define DMODEL 1024
#define NHEAD 16
#define DHEAD 64

__device__ __forceinline__ float to_tf32(float a) {
    float r;
    asm("cvt.rna.tf32.f32 %0, %1;" : "=f"(r) : "f"(a));
    return r;
}
__device__ __forceinline__ float4 round4(float4 v) {
    v.x = to_tf32(v.x); v.y = to_tf32(v.y);
    v.z = to_tf32(v.z); v.w = to_tf32(v.w);
    return v;
}
__device__ __forceinline__ uint32_t smem_u32(const void* p) {
    uint32_t a;
    asm("{ .reg .u64 t; cvta.to.shared.u64 t, %1; cvt.u32.u64 %0, t; }"
        : "=r"(a) : "l"(p));
    return a;
}
__device__ __forceinline__ void cp16(uint32_t dst_smem, const void* src) {
    asm volatile("cp.async.cg.shared.global [%0], [%1], 16;"
                 :: "r"(dst_smem), "l"(src));
}
#define CP_COMMIT() asm volatile("cp.async.commit_group;" ::: "memory")
#define CP_WAIT2()  asm volatile("cp.async.wait_group 2;" ::: "memory")

// m16n8k8 tf32 mma, canonical fragment order (g=lane>>2, t=lane&3):
// a0=A[g][t] a1=A[g+8][t] a2=A[g][t+4] a3=A[g+8][t+4]
// b0=B[k=t][n=g] b1=B[k=t+4][n=g]
// c0=(g,2t) c1=(g,2t+1) c2=(g+8,2t) c3=(g+8,2t+1)
__device__ __forceinline__ void mma8(float* c, const uint32_t* a,
                                     uint32_t b0, uint32_t b1) {
    asm volatile(
        "mma.sync.aligned.m16n8k8.row.col.f32.tf32.tf32.f32 "
        "{%0,%1,%2,%3}, {%4,%5,%6,%7}, {%8,%9}, {%0,%1,%2,%3};"
        : "+f"(c[0]), "+f"(c[1]), "+f"(c[2]), "+f"(c[3])
        : "r"(a[0]), "r"(a[1]), "r"(a[2]), "r"(a[3]), "r"(b0), "r"(b1));
}

// ===========================================================================
// Scratch. q stored tf32-rounded AND pre-scaled by 0.125 (exact binade
// shift). k, v tf32-rounded. g_xt = tf32-rounded x. g_er = tf32 Er.
// ===========================================================================
__device__ float g_q[BATCH * NHEAD * SEQ * DHEAD];
__device__ float g_k[BATCH * NHEAD * SEQ * DHEAD];
__device__ float g_v[BATCH * NHEAD * SEQ * DHEAD];
__device__ float g_xt[BATCH * SEQ * DMODEL];
__device__ float g_er[SEQ * DHEAD];
__device__ float g_wt[3 * DMODEL * DMODEL];

// ===========================================================================
// Prep kernels
// ===========================================================================
__global__ __launch_bounds__(256) void prep_x_kernel(const float* __restrict__ x)
{
    int i = blockIdx.x * 256 + threadIdx.x;
    ((float4*)g_xt)[i] = round4(((const float4*)x)[i]);
}

__global__ __launch_bounds__(256) void prep_w_kernel(
    const float* __restrict__ W0, const float* __restrict__ W1,
    const float* __restrict__ W2)
{
    __shared__ float t[32][33];
    const int z = blockIdx.z;
    const float* W = (z == 0) ? W0 : (z == 1) ? W1 : W2;
    float* WT = g_wt + (size_t)z * DMODEL * DMODEL;
    const int n0 = blockIdx.x * 32;
    const int k0 = blockIdx.y * 32;
    const int tx = threadIdx.x & 31;
    const int ty = threadIdx.x >> 5;
    #pragma unroll
    for (int r = 0; r < 4; r++)
        t[ty + 8 * r][tx] = to_tf32(W[(size_t)(k0 + ty + 8 * r) * DMODEL + n0 + tx]);
    __syncthreads();
    #pragma unroll
    for (int r = 0; r < 4; r++)
        WT[(size_t)(n0 + ty + 8 * r) * DMODEL + k0 + tx] = t[tx][ty + 8 * r];
}

__global__ __launch_bounds__(256) void prep_er_kernel(const float* __restrict__ Er)
{
    int i = blockIdx.x * 256 + threadIdx.x;
    ((float4*)g_er)[i] = round4(((const float4*)Er)[i]);
}

// ===========================================================================
// QKV GEMM via mma.sync tf32, v6: cp.async 4-stage pipeline, TKT=16,
// 2 CTAs/SM. Stages are PLAIN ROW-MAJOR A[128x16] | B[128x16] (contiguous
// copies). Fragments use the k-permutation chunk-pairing validated in the
// attention QK loop: one float4 feeds both k-chunks (chunk0 <- elems 4t,
// 4t+1; chunk1 <- 4t+2,4t+3), applied identically to A and B.
// ===========================================================================
#define TKT 16
#define NKT (DMODEL / TKT)        // 64
#define NSTG 4
#define STAGEF 4096               // floats per stage (A 2048 + B 2048)

__global__ __launch_bounds__(256, 2) void qkv_gemm_mma_kernel(
    const float* __restrict__ b0v, const float* __restrict__ b1v,
    const float* __restrict__ b2v)
{
    extern __shared__ float smf[];
    const uint32_t smb = smem_u32(smf);

    const int z  = blockIdx.z;
    const int m0 = blockIdx.y * 128;
    const int n0 = blockIdx.x * 128;
    const float* bias = (z == 0) ? b0v : (z == 1) ? b1v : b2v;
    float* outp       = (z == 0) ? g_q : (z == 1) ? g_k : g_v;
    const float* WT   = g_wt + (size_t)z * DMODEL * DMODEL;
    const float sc    = (z == 0) ? 0.125f : 1.0f;

    const int tid = threadIdx.x;
    const int wid = tid >> 5;
    const int lid = tid & 31;
    const int warp_m = wid >> 1;      // 0..3: 32 rows
    const int warp_n = wid & 1;       // 0..1: 64 cols
    const int g = lid >> 2;
    const int t = lid & 3;

    float acc[2][8][4];
    #pragma unroll
    for (int a = 0; a < 2; a++)
        #pragma unroll
        for (int n = 0; n < 8; n++)
            #pragma unroll
            for (int c = 0; c < 4; c++) acc[a][n][c] = 0.f;

    // staging decode: 2 A quarters + 2 B quarters per thread
    // item f (0..511): row = f>>2, quarter q4 = f&3
    const int r0 = tid >> 2;            // rows for f = tid
    const int q0 = tid & 3;
    const int r1 = (tid + 256) >> 2;    // rows for f = tid+256
    const int q1 = (tid + 256) & 3;

    auto issue_tile = [&](int ktile, int stg) {
        const int kt = ktile * TKT;
        const uint32_t sb = smb + (uint32_t)(stg * STAGEF) * 4u;
        cp16(sb + (uint32_t)(r0 * 16 + q0 * 4) * 4u,
             &g_xt[(size_t)(m0 + r0) * DMODEL + kt + q0 * 4]);
        cp16(sb + (uint32_t)(r1 * 16 + q1 * 4) * 4u,
             &g_xt[(size_t)(m0 + r1) * DMODEL + kt + q1 * 4]);
        cp16(sb + (uint32_t)(2048 + r0 * 16 + q0 * 4) * 4u,
             &WT[(size_t)(n0 + r0) * DMODEL + kt + q0 * 4]);
        cp16(sb + (uint32_t)(2048 + r1 * 16 + q1 * 4) * 4u,
             &WT[(size_t)(n0 + r1) * DMODEL + kt + q1 * 4]);
    };

    // ---- prologue: issue stages 0..2 ----
    #pragma unroll
    for (int s = 0; s < 3; s++) {
        issue_tile(s, s);
        CP_COMMIT();
    }

    for (int ktile = 0; ktile < NKT; ktile++) {
        CP_WAIT2();          // group for tile 'ktile' complete (in-order)
        __syncthreads();     // visible to all threads

        const float* Ap = smf + (ktile & 3) * STAGEF;
        const float* Bp = Ap + 2048;

        // A fragments: two float4 per m-block (rows base+g, base+g+8)
        uint32_t af[2][2][4];   // [mb][chunk][4]
        #pragma unroll
        for (int mb = 0; mb < 2; mb++) {
            const int base = warp_m * 32 + mb * 16;
            const float4 fa0 = *(const float4*)&Ap[(base + g) * 16 + 4 * t];
            const float4 fa1 = *(const float4*)&Ap[(base + g + 8) * 16 + 4 * t];
            af[mb][0][0] = __float_as_uint(fa0.x); af[mb][0][1] = __float_as_uint(fa1.x);
            af[mb][0][2] = __float_as_uint(fa0.y); af[mb][0][3] = __float_as_uint(fa1.y);
            af[mb][1][0] = __float_as_uint(fa0.z); af[mb][1][1] = __float_as_uint(fa1.z);
            af[mb][1][2] = __float_as_uint(fa0.w); af[mb][1][3] = __float_as_uint(fa1.w);
        }
        #pragma unroll
        for (int bp = 0; bp < 8; bp++) {
            const uint4 vb = *(const uint4*)&Bp[(warp_n * 64 + 8 * bp + g) * 16 + 4 * t];
            #pragma unroll
            for (int mb = 0; mb < 2; mb++) {
                mma8(acc[mb][bp], af[mb][0], vb.x, vb.y);
                mma8(acc[mb][bp], af[mb][1], vb.z, vb.w);
            }
        }

        // issue tile ktile+3 into its stage (buffer freed at barrier above)
        if (ktile + 3 < NKT) {
            issue_tile(ktile + 3, (ktile + 3) & 3);
            CP_COMMIT();
        } else {
            CP_COMMIT();     // empty group keeps wait_group counting exact
        }
    }

    // ---- epilogue: bias + tf32 round (+1/8 for q) + scatter to (b,h,s,d) ----
    #pragma unroll
    for (int mb = 0; mb < 2; mb++) {
        const int mA = m0 + warp_m * 32 + mb * 16 + g;
        const int bA = mA >> 11;
        const int sA = mA & (SEQ - 1);
        const int sB = (mA + 8) & (SEQ - 1);
        #pragma unroll
        for (int bp = 0; bp < 8; bp++) {
            const int n = n0 + warp_n * 64 + bp * 8 + t * 2;
            const int h = n >> 6;
            const int d = n & 63;
            const float2 bb = *(const float2*)&bias[n];
            float* p0 = &outp[(((size_t)(bA * NHEAD + h)) * SEQ + sA) * DHEAD + d];
            float* p1 = &outp[(((size_t)(bA * NHEAD + h)) * SEQ + sB) * DHEAD + d];
            *(float2*)p0 = make_float2(to_tf32((acc[mb][bp][0] + bb.x) * sc),
                                       to_tf32((acc[mb][bp][1] + bb.y) * sc));
            *(float2*)p1 = make_float2(to_tf32((acc[mb][bp][2] + bb.x) * sc),
                                       to_tf32((acc[mb][bp][3] + bb.y) * sc));
        }
    }
}

// ===========================================================================
// Relative-position causal flash attention, mma.sync tf32 (R13/R15 winner,
// reverted verbatim). Uniform windowed REL: warp wid gathers band blocks
// starting at c0b = 14-2wid, 3 chunks x 6 blocks, compile-time trip counts.
// SMEM: k[128x80] | vT[64x144, XOR-swizzle] | band[256x80]/P[128x144] |
//       G[128x72] (warp-private rows; 48 cols used/chunk).
// ===========================================================================
#define KP  80
#define VP  144
#define BP  80
#define PPL 144
#define GP  72
#define OFF_K   0
#define OFF_VT  10240              // 128*80
#define OFF_BPD 19456              // + 64*144
#define OFF_G   39936              // + 256*80
#define ATT_FLOATS 49152           // + 128*72
#define ATT_SMEM (ATT_FLOATS * 4)  // 196608

__global__ __launch_bounds__(256, 1) void relattn_mma_kernel(float* __restrict__ out)
{
    extern __shared__ float sm[];
    float* k_s  = sm + OFF_K;
    float* vt_s = sm + OFF_VT;
    float* bp_s = sm + OFF_BPD;     // band, then P (band dead after REL)
    float* g_s  = sm + OFF_G;

    const int sb = (int)gridDim.x - 1 - (int)blockIdx.x;  // heavy first
    const int bh = blockIdx.y;
    const int b  = bh >> 4;
    const int h  = bh & 15;
    const int s0 = sb * 128;

    const float* Q = g_q + (size_t)bh * SEQ * DHEAD;
    const float* K = g_k + (size_t)bh * SEQ * DHEAD;
    const float* V = g_v + (size_t)bh * SEQ * DHEAD;

    const int tid = threadIdx.x;
    const int wid = tid >> 5;
    const int lid = tid & 31;
    const int g = lid >> 2;
    const int t = lid & 3;
    const int i0 = wid * 16 + g;
    const int i1 = i0 + 8;
    const int c0b = 14 - 2 * wid;      // REL window start block (warp-uniform)

    // ---- persistent q fragments (already tf32 + 1/8-scaled) ----
    uint32_t qf[8][4];
    #pragma unroll
    for (int u = 0; u < 4; u++) {
        float4 q0 = *(const float4*)&Q[(size_t)(s0 + i0) * DHEAD + 16 * u + 4 * t];
        float4 q1 = *(const float4*)&Q[(size_t)(s0 + i1) * DHEAD + 16 * u + 4 * t];
        qf[2 * u][0] = __float_as_uint(q0.x); qf[2 * u][1] = __float_as_uint(q1.x);
        qf[2 * u][2] = __float_as_uint(q0.y); qf[2 * u][3] = __float_as_uint(q1.y);
        qf[2 * u + 1][0] = __float_as_uint(q0.z); qf[2 * u + 1][1] = __float_as_uint(q1.z);
        qf[2 * u + 1][2] = __float_as_uint(q0.w); qf[2 * u + 1][3] = __float_as_uint(q1.w);
    }

    float m_[2] = {-1e30f, -1e30f};
    float l_[2] = {0.f, 0.f};
    float acc_o[8][4];
    #pragma unroll
    for (int n8 = 0; n8 < 8; n8++)
        #pragma unroll
        for (int c = 0; c < 4; c++) acc_o[n8][c] = 0.f;

    const float4* Er4 = (const float4*)g_er;

    for (int t0 = 0; t0 <= s0; t0 += 128) {
        const bool diag = (t0 == s0);
        __syncthreads();   // prior tile reads of k/vT/band-P done

        // ---- stage k, vT (swizzled transpose), band (all pre-rounded) ----
        {
            const float4* K4 = (const float4*)(K + (size_t)t0 * DHEAD);
            const float4* V4 = (const float4*)(V + (size_t)t0 * DHEAD);
            #pragma unroll
            for (int u = 0; u < 8; u++) {
                int f = tid + u * 256;
                int row = f >> 4, c4 = f & 15;
                *(float4*)&k_s[row * KP + c4 * 4] = K4[row * 16 + c4];
                float4 vv = V4[row * 16 + c4];
                int sw = row ^ (4 * (c4 & 3));
                vt_s[(4 * c4 + 0) * VP + sw] = vv.x;
                vt_s[(4 * c4 + 1) * VP + sw] = vv.y;
                vt_s[(4 * c4 + 2) * VP + sw] = vv.z;
                vt_s[(4 * c4 + 3) * VP + sw] = vv.w;
            }
            int l0 = t0 - s0 + (SEQ - 1) - 127;
            #pragma unroll
            for (int u = 0; u < 16; u++) {
                int f = tid + u * 256;
                int r = f >> 4, c4 = f & 15;
                int gl = l0 + r;
                gl = gl > SEQ - 1 ? SEQ - 1 : gl;
                *(float4*)&bp_s[r * BP + c4 * 4] = Er4[gl * 16 + c4];
            }
        }
        __syncthreads();

        // ---- QK ----
        float acc_s[16][4];
        #pragma unroll
        for (int n8 = 0; n8 < 16; n8++)
            #pragma unroll
            for (int c = 0; c < 4; c++) acc_s[n8][c] = 0.f;

        #pragma unroll
        for (int u = 0; u < 4; u++) {
            #pragma unroll
            for (int n8 = 0; n8 < 16; n8++) {
                if (diag && n8 > 2 * wid + 1) continue;
                const uint4 kb = *(const uint4*)&k_s[(8 * n8 + g) * KP + 16 * u + 4 * t];
                mma8(acc_s[n8], qf[2 * u],     kb.x, kb.y);
                mma8(acc_s[n8], qf[2 * u + 1], kb.z, kb.w);
            }
        }

        // ---- REL: uniform windowed G (3 chunks x 6 blocks) + gather ----
        #pragma unroll
        for (int ck = 0; ck < 3; ck++) {
            float acc_g[6][4];
            #pragma unroll
            for (int n6 = 0; n6 < 6; n6++)
                #pragma unroll
                for (int cc = 0; cc < 4; cc++) acc_g[n6][cc] = 0.f;

            const int bbase = c0b + 6 * ck;     // warp-uniform
            #pragma unroll
            for (int u = 0; u < 4; u++)
                #pragma unroll
                for (int n6 = 0; n6 < 6; n6++) {
                    const uint4 bb = *(const uint4*)
                        &bp_s[(8 * (bbase + n6) + g) * BP + 16 * u + 4 * t];
                    mma8(acc_g[n6], qf[2 * u],     bb.x, bb.y);
                    mma8(acc_g[n6], qf[2 * u + 1], bb.z, bb.w);
                }

            __syncwarp();   // prior chunk's gather reads done
            #pragma unroll
            for (int n6 = 0; n6 < 6; n6++) {
                *(float2*)&g_s[i0 * GP + 8 * n6 + 2 * t] = make_float2(acc_g[n6][0], acc_g[n6][1]);
                *(float2*)&g_s[i1 * GP + 8 * n6 + 2 * t] = make_float2(acc_g[n6][2], acc_g[n6][3]);
            }
            __syncwarp();

            // gather: lp = j - g + 15 - 48*ck (warp-independent)
            const int lpb = 2 * t - g + 15 - 48 * ck;
            #pragma unroll
            for (int n8 = 0; n8 < 16; n8++) {
                if (diag && n8 > 2 * wid + 1) continue;
                int lp0 = 8 * n8 + lpb;        // row i0
                int lp1 = lp0 - 8;             // row i1
                if (lp0 >= 0 && lp0 < 48)         acc_s[n8][0] += g_s[i0 * GP + lp0];
                if (lp0 + 1 >= 0 && lp0 + 1 < 48) acc_s[n8][1] += g_s[i0 * GP + lp0 + 1];
                if (lp1 >= 0 && lp1 < 48)         acc_s[n8][2] += g_s[i1 * GP + lp1];
                if (lp1 + 1 >= 0 && lp1 + 1 < 48) acc_s[n8][3] += g_s[i1 * GP + lp1 + 1];
            }
        }
        __syncthreads();   // ALL band reads done before P overwrites bp_s

        // ---- mask + row max (scale folded into q) ----
        float mx0 = -1e30f, mx1 = -1e30f;
        #pragma unroll
        for (int n8 = 0; n8 < 16; n8++) {
            int j = 8 * n8 + 2 * t;
            float v0 = acc_s[n8][0];
            float v1 = acc_s[n8][1];
            float v2 = acc_s[n8][2];
            float v3 = acc_s[n8][3];
            if (diag) {
                if (j     > i0) v0 = -1e30f;
                if (j + 1 > i0) v1 = -1e30f;
                if (j     > i1) v2 = -1e30f;
                if (j + 1 > i1) v3 = -1e30f;
            }
            acc_s[n8][0] = v0; acc_s[n8][1] = v1;
            acc_s[n8][2] = v2; acc_s[n8][3] = v3;
            mx0 = fmaxf(mx0, fmaxf(v0, v1));
            mx1 = fmaxf(mx1, fmaxf(v2, v3));
        }
        mx0 = fmaxf(mx0, __shfl_xor_sync(0xffffffffu, mx0, 1));
        mx0 = fmaxf(mx0, __shfl_xor_sync(0xffffffffu, mx0, 2));
        mx1 = fmaxf(mx1, __shfl_xor_sync(0xffffffffu, mx1, 1));
        mx1 = fmaxf(mx1, __shfl_xor_sync(0xffffffffu, mx1, 2));

        // ---- online softmax; write P (tf32) to warp-private rows ----
        float mn0 = fmaxf(m_[0], mx0);
        float mn1 = fmaxf(m_[1], mx1);
        float al0 = __expf(m_[0] - mn0);
        float al1 = __expf(m_[1] - mn1);
        m_[0] = mn0; m_[1] = mn1;
        float ls0 = 0.f, ls1 = 0.f;
        #pragma unroll
        for (int n8 = 0; n8 < 16; n8++) {
            int j = 8 * n8 + 2 * t;
            float p0 = to_tf32(__expf(acc_s[n8][0] - mn0));
            float p1 = to_tf32(__expf(acc_s[n8][1] - mn0));
            float p2 = to_tf32(__expf(acc_s[n8][2] - mn1));
            float p3 = to_tf32(__expf(acc_s[n8][3] - mn1));
            ls0 += p0 + p1;
            ls1 += p2 + p3;
            *(float2*)&bp_s[i0 * PPL + j] = make_float2(p0, p1);
            *(float2*)&bp_s[i1 * PPL + j] = make_float2(p2, p3);
        }
        ls0 += __shfl_xor_sync(0xffffffffu, ls0, 1);
        ls0 += __shfl_xor_sync(0xffffffffu, ls0, 2);
        ls1 += __shfl_xor_sync(0xffffffffu, ls1, 1);
        ls1 += __shfl_xor_sync(0xffffffffu, ls1, 2);
        l_[0] = l_[0] * al0 + ls0;
        l_[1] = l_[1] * al1 + ls1;
        #pragma unroll
        for (int n8 = 0; n8 < 8; n8++) {
            acc_o[n8][0] *= al0; acc_o[n8][1] *= al0;
            acc_o[n8][2] *= al1; acc_o[n8][3] *= al1;
        }
        __syncwarp();   // P rows visible within warp

        // ---- PV: O += P @ V, chunk-paired float4 loads ----
        #pragma unroll
        for (int u = 0; u < 8; u++) {
            if (diag && u > wid) continue;
            const float4 p0 = *(const float4*)&bp_s[i0 * PPL + 16 * u + 4 * t];
            const float4 p1 = *(const float4*)&bp_s[i1 * PPL + 16 * u + 4 * t];
            uint32_t pfA[4] = {__float_as_uint(p0.x), __float_as_uint(p1.x),
                               __float_as_uint(p0.y), __float_as_uint(p1.y)};
            uint32_t pfB[4] = {__float_as_uint(p0.z), __float_as_uint(p1.z),
                               __float_as_uint(p0.w), __float_as_uint(p1.w)};
            #pragma unroll
            for (int n8 = 0; n8 < 8; n8++) {
                int d = 8 * n8 + g;
                int xr = 4 * ((d >> 2) & 3);
                const uint4 vb = *(const uint4*)&vt_s[d * VP + (16 * u + ((4 * t) ^ xr))];
                mma8(acc_o[n8], pfA, vb.x, vb.y);
                mma8(acc_o[n8], pfB, vb.z, vb.w);
            }
        }
        __syncwarp();   // P reads done before next tile overwrites bp_s
    }

    // ---- epilogue ----
    float inv0 = 1.f / l_[0];
    float inv1 = 1.f / l_[1];
    #pragma unroll
    for (int n8 = 0; n8 < 8; n8++) {
        int d = 8 * n8 + 2 * t;
        int sg0 = s0 + i0;
        int sg1 = s0 + i1;
        *(float2*)&out[((size_t)b * SEQ + sg0) * DMODEL + h * DHEAD + d] =
            make_float2(acc_o[n8][0] * inv0, acc_o[n8][1] * inv0);
        *(float2*)&out[((size_t)b * SEQ + sg1) * DMODEL + h * DHEAD + d] =
            make_float2(acc_o[n8][2] * inv1, acc_o[n8][3] * inv1);
    }
}

// ===========================================================================
extern "C" void kernel_launch(void* const* d_in, const int* in_sizes, int n_in,
                              void* d_out, int out_size)
{
    const float* x  = (const float*)d_in[0];
    const float* Wq = (const float*)d_in[1];
    const float* bq = (const float*)d_in[2];
    const float* Wk = (const float*)d_in[3];
    const float* bk = (const float*)d_in[4];
    const float* Wv = (const float*)d_in[5];
    const float* bv = (const float*)d_in[6];
    const float* Er = (const float*)d_in[7];
    float* out = (float*)d_out;

    (void)in_sizes; (void)n_in; (void)out_size;

    cudaFuncSetAttribute(relattn_mma_kernel,
                         cudaFuncAttributeMaxDynamicSharedMemorySize, ATT_SMEM);
    const int gemm_smem = NSTG * STAGEF * 4;   // 65536
    cudaFuncSetAttribute(qkv_gemm_mma_kernel,
                         cudaFuncAttributeMaxDynamicSharedMemorySize, gemm_smem);

    prep_x_kernel<<<(BATCH * SEQ * DMODEL) / (4 * 256), 256>>>(x);
    prep_w_kernel<<<dim3(DMODEL / 32, DMODEL / 32, 3), 256>>>(Wq, Wk, Wv);
    prep_er_kernel<<<(SEQ * DHEAD) / (4 * 256), 256>>>(Er);

    dim3 gg(DMODEL / 128, (BATCH * SEQ) / 128, 3);
    qkv_gemm_mma_kernel<<<gg, 256, gemm_smem>>>(bq, bk, bv);

    dim3 g2(SEQ / 128, BATCH * NHEAD);
    relattn_mma_kernel<<<g2, 256, ATT_SMEM>>>(out);
}